// round 16
// baseline (speedup 1.0000x reference)
#include <cuda_runtime.h>
#include <cstddef>
#include <cstdint>

// Problem constants
#define BATCH 2
#define TT    1024
#define DM    1024
#define NH    16
#define TD    5
#define DH    64
#define PCOLS (NH * TD)   // 80

// Scratch (no allocation allowed -> __device__ globals)
__device__ float g_P[BATCH * TT * PCOLS];    // sigmoid(x@Wp + bp), (B*T, 80)
__device__ float g_V[BATCH * TT * DM];       // x@Wv,  (B*T, 1024)
__device__ float g_CTX[BATCH * TT * DM];     // attn@V reassembled, (B*T, 1024)

// ---------------------------------------------------------------------------
// tf32 helpers
// ---------------------------------------------------------------------------
__device__ __forceinline__ uint32_t f2tf32(float x) {
    uint32_t r;
    asm("cvt.rna.tf32.f32 %0, %1;" : "=r"(r) : "f"(x));
    return r;
}

__device__ __forceinline__ void mma_tf32(float4& c, const uint32_t a[4],
                                         const uint32_t b0, const uint32_t b1) {
    asm volatile(
        "mma.sync.aligned.m16n8k8.row.col.f32.tf32.tf32.f32 "
        "{%0,%1,%2,%3}, {%4,%5,%6,%7}, {%8,%9}, {%0,%1,%2,%3};"
        : "+f"(c.x), "+f"(c.y), "+f"(c.z), "+f"(c.w)
        : "r"(a[0]), "r"(a[1]), "r"(a[2]), "r"(a[3]), "r"(b0), "r"(b1));
}

// exp(x) for x in (0,1]: e^x = e^0.5 * Taylor6(x-0.5).  |err| ~1.6e-6.
__device__ __forceinline__ float exp01(float x) {
    const float t = x - 0.5f;
    float p = fmaf(t, 1.388888889e-3f, 8.333333333e-3f);
    p = fmaf(p, t, 4.166666667e-2f);
    p = fmaf(p, t, 1.666666667e-1f);
    p = fmaf(p, t, 0.5f);
    p = fmaf(p, t, 1.0f);
    p = fmaf(p, t, 1.0f);
    return 1.6487212707f * p;
}

// ---------------------------------------------------------------------------
// tf32 tensor-core GEMM: C[*,N] = A[*,K] @ B[K,N] (+bias+sigmoid if SIG).
// 128x64 block tile, BK=16, 256 threads = 8 warps (4m x 2n), warp tile 32x32.
// Small tile -> >=256 blocks -> 2 CTAs/SM (4 warps/SMSP) for latency hiding.
// ---------------------------------------------------------------------------
#define BKt 16
#define APAD 136        // A smem stride over m (128 + 8 skew)
#define BPAD 72         // B smem stride over n (64 + 8 skew)
#define TS_A(st, k, m) sA[((st) * BKt + (k)) * APAD + (m)]
#define TS_B(st, k, n) sB[((st) * BKt + (k)) * BPAD + (n)]

template<int N, int K, bool SIG>
__device__ __forceinline__ void tgemm_body(const float* __restrict__ A,
                                           const float* __restrict__ B,
                                           const float* __restrict__ bias,
                                           float* __restrict__ C,
                                           int bm, int bn,
                                           uint32_t* sA, uint32_t* sB)
{
    const int tid  = threadIdx.x;          // 0..255
    const int lane = tid & 31;
    const int wid  = tid >> 5;             // 0..7
    const int g    = lane >> 2;
    const int t    = lane & 3;
    const int wm   = (wid >> 1) * 32;      // 4 warp rows
    const int wn   = (wid & 1) * 32;       // 2 warp cols

    // loader indices
    const int ar = tid >> 2, ac = (tid & 3) * 4;    // A: 128x16, 2 float4/thr
    const int brr = tid >> 4, bcc = (tid & 15) * 4; // B: 16x64, 1 float4/thr

    // ---- initial tile -> stage 0
    {
        #pragma unroll
        for (int i = 0; i < 2; i++) {
            int f = tid + i * 256, r = f >> 2, c = (f & 3) * 4;
            float4 v = *(const float4*)(A + (size_t)(bm + r) * K + c);
            TS_A(0, c + 0, r) = f2tf32(v.x);
            TS_A(0, c + 1, r) = f2tf32(v.y);
            TS_A(0, c + 2, r) = f2tf32(v.z);
            TS_A(0, c + 3, r) = f2tf32(v.w);
        }
        float4 v = (bn + bcc < N)
                 ? *(const float4*)(B + (size_t)brr * N + bn + bcc)
                 : make_float4(0.f, 0.f, 0.f, 0.f);
        TS_B(0, brr, bcc + 0) = f2tf32(v.x);
        TS_B(0, brr, bcc + 1) = f2tf32(v.y);
        TS_B(0, brr, bcc + 2) = f2tf32(v.z);
        TS_B(0, brr, bcc + 3) = f2tf32(v.w);
    }
    __syncthreads();

    float4 acc[2][4];
    #pragma unroll
    for (int mi = 0; mi < 2; mi++)
        #pragma unroll
        for (int ni = 0; ni < 4; ni++)
            acc[mi][ni] = make_float4(0.f, 0.f, 0.f, 0.f);

    float4 pa[2], pb;
    int cur = 0;
    for (int k0 = 0; k0 < K; k0 += BKt) {
        const bool more = (k0 + BKt) < K;
        if (more) {   // prefetch next tile into registers (raw fp32)
            #pragma unroll
            for (int i = 0; i < 2; i++) {
                int f = tid + i * 256, r = f >> 2, c = (f & 3) * 4;
                pa[i] = *(const float4*)(A + (size_t)(bm + r) * K + k0 + BKt + c);
            }
            pb = (bn + bcc < N)
               ? *(const float4*)(B + (size_t)(k0 + BKt + brr) * N + bn + bcc)
               : make_float4(0.f, 0.f, 0.f, 0.f);
        }
        // ---- compute on current stage: 2 k8 sub-steps
        #pragma unroll
        for (int s = 0; s < 2; s++) {
            const int kb = s * 8;
            uint32_t af[2][4], bf[4][2];
            #pragma unroll
            for (int mi = 0; mi < 2; mi++) {
                const int m0 = wm + mi * 16;
                af[mi][0] = TS_A(cur, kb + t,     m0 + g);
                af[mi][1] = TS_A(cur, kb + t,     m0 + g + 8);
                af[mi][2] = TS_A(cur, kb + t + 4, m0 + g);
                af[mi][3] = TS_A(cur, kb + t + 4, m0 + g + 8);
            }
            #pragma unroll
            for (int ni = 0; ni < 4; ni++) {
                const int n0 = wn + ni * 8;
                bf[ni][0] = TS_B(cur, kb + t,     n0 + g);
                bf[ni][1] = TS_B(cur, kb + t + 4, n0 + g);
            }
            #pragma unroll
            for (int mi = 0; mi < 2; mi++)
                #pragma unroll
                for (int ni = 0; ni < 4; ni++)
                    mma_tf32(acc[mi][ni], af[mi], bf[ni][0], bf[ni][1]);
        }
        if (more) {   // commit prefetched tile to the other stage
            int nxt = cur ^ 1;
            #pragma unroll
            for (int i = 0; i < 2; i++) {
                int f = tid + i * 256, r = f >> 2, c = (f & 3) * 4;
                TS_A(nxt, c + 0, r) = f2tf32(pa[i].x);
                TS_A(nxt, c + 1, r) = f2tf32(pa[i].y);
                TS_A(nxt, c + 2, r) = f2tf32(pa[i].z);
                TS_A(nxt, c + 3, r) = f2tf32(pa[i].w);
            }
            TS_B(nxt, brr, bcc + 0) = f2tf32(pb.x);
            TS_B(nxt, brr, bcc + 1) = f2tf32(pb.y);
            TS_B(nxt, brr, bcc + 2) = f2tf32(pb.z);
            TS_B(nxt, brr, bcc + 3) = f2tf32(pb.w);
            __syncthreads();
            cur = nxt;
        }
    }

    // ---- epilogue from fragments (float2 stores)
    #pragma unroll
    for (int mi = 0; mi < 2; mi++) {
        const int r0 = bm + wm + mi * 16 + g;
        #pragma unroll
        for (int ni = 0; ni < 4; ni++) {
            const int col = bn + wn + ni * 8 + 2 * t;
            if (col < N) {
                float2 lo = make_float2(acc[mi][ni].x, acc[mi][ni].y);
                float2 hi = make_float2(acc[mi][ni].z, acc[mi][ni].w);
                if (SIG) {
                    lo.x = 1.f / (1.f + __expf(-(lo.x + bias[col + 0])));
                    lo.y = 1.f / (1.f + __expf(-(lo.y + bias[col + 1])));
                    hi.x = 1.f / (1.f + __expf(-(hi.x + bias[col + 0])));
                    hi.y = 1.f / (1.f + __expf(-(hi.y + bias[col + 1])));
                }
                *(float2*)(C + (size_t)r0 * N + col)       = lo;
                *(float2*)(C + (size_t)(r0 + 8) * N + col) = hi;
            }
        }
    }
}

// Fused V + P GEMM. V: 2048x1024 in 128x64 tiles = 256 blocks (bid>>4 = m,
// bid&15 = n). P: 2048x80 in 128x64 tiles = 32 blocks. 288 blocks -> 2 CTAs/SM.
__global__ __launch_bounds__(256)
void gemm_vp_kernel(const float* __restrict__ x, const float* __restrict__ Wv,
                    const float* __restrict__ Wp, const float* __restrict__ bp)
{
    __shared__ uint32_t sA[2 * BKt * APAD];
    __shared__ uint32_t sB[2 * BKt * BPAD];
    const int bid = blockIdx.x;
    if (bid < 256)
        tgemm_body<DM, DM, false>(x, Wv, nullptr, g_V,
                                  (bid >> 4) * 128, (bid & 15) * 64, sA, sB);
    else {
        const int pbid = bid - 256;
        tgemm_body<PCOLS, DM, true>(x, Wp, bp, g_P,
                                    (pbid >> 1) * 128, (pbid & 1) * 64, sA, sB);
    }
}

__global__ __launch_bounds__(256)
void gemm_o_kernel(const float* __restrict__ Wo, float* __restrict__ out)
{
    __shared__ uint32_t sA[2 * BKt * APAD];
    __shared__ uint32_t sB[2 * BKt * BPAD];
    tgemm_body<DM, DM, false>(g_CTX, Wo, nullptr, out,
                              blockIdx.y * 128, blockIdx.x * 64, sA, sB);
}

// ---------------------------------------------------------------------------
// Attention with tensor-core PV (validated R14 config, unchanged).
// ---------------------------------------------------------------------------
#define ES_STRIDE 68
#define VT_STRIDE 72

__global__ __launch_bounds__(256)
void attn_kernel()
{
    __shared__ uint32_t Es[64 * ES_STRIDE];   // exp-sim, tf32, row-major [q][k]
    __shared__ uint32_t Vt[64 * VT_STRIDE];   // V tile, tf32 [k][d]
    __shared__ float    kpT[TD][64];          // transposed key paths
    __shared__ float    den4[64][4];          // per-row denom partials

    const int bh = blockIdx.y;
    const int b  = bh >> 4;
    const int h  = bh & 15;
    const int qb = gridDim.x - 1 - blockIdx.x;   // heavy blocks first
    const int tid = threadIdx.x;
    const int lane = tid & 31;
    const int wid  = tid >> 5;
    const int g    = lane >> 2;
    const int t    = lane & 3;

    const int q1 = tid >> 2;
    const int kt = tid & 3;
    const int qg1 = qb * 64 + q1;
    const int wm4 = (wid >> 1) * 16;
    const int nb  = (wid & 1) * 32;

    const int vr0 = tid >> 4;
    const int vc4 = tid & 15;
    const int kd  = tid >> 6;
    const int kkk = tid & 63;

    float uq[TD], vq[TD];
    {
        const float* prow = g_P + (size_t)(b * TT + qg1) * PCOLS + h * TD;
        #pragma unroll
        for (int d = 0; d < TD; d++) {
            float p = prow[d];
            uq[d] = 2.f * p - 1.f;
            vq[d] = 1.f - p;
        }
    }

    float4 acc[4];
    #pragma unroll
    for (int i = 0; i < 4; i++) acc[i] = make_float4(0.f, 0.f, 0.f, 0.f);
    float denLocal = 0.f;

    float4 pv[4];
    float  pk0 = 0.f, pk1 = 0.f;

    #define PREFETCH(k0_)                                                      \
    {                                                                          \
        _Pragma("unroll")                                                      \
        for (int i = 0; i < 4; i++) {                                          \
            pv[i] = *(const float4*)(g_V + (size_t)(b * TT + (k0_) + vr0 +     \
                                     i * 16) * DM + h * DH + vc4 * 4);         \
        }                                                                      \
        pk0 = g_P[(size_t)(b * TT + (k0_) + kkk) * PCOLS + h * TD + kd];       \
        if (tid < 64)                                                          \
            pk1 = g_P[(size_t)(b * TT + (k0_) + tid) * PCOLS + h * TD + 4];    \
    }

    #define COMMIT()                                                           \
    {                                                                          \
        _Pragma("unroll")                                                      \
        for (int i = 0; i < 4; i++) {                                          \
            uint32_t* dst = &Vt[(vr0 + i * 16) * VT_STRIDE + vc4 * 4];         \
            dst[0] = f2tf32(pv[i].x); dst[1] = f2tf32(pv[i].y);                \
            dst[2] = f2tf32(pv[i].z); dst[3] = f2tf32(pv[i].w);                \
        }                                                                      \
        kpT[kd][kkk] = pk0;                                                    \
        if (tid < 64) kpT[4][tid] = pk1;                                       \
    }

    PREFETCH(0)
    COMMIT()
    __syncthreads();

    for (int kb = 0; kb <= qb; kb++) {
        const int k0 = kb * 64;

        #pragma unroll
        for (int j = 0; j < 16; j++) {
            const int k = kt * 16 + j;
            float cp = 1.f, s = 0.f;
            #pragma unroll
            for (int d = 0; d < TD; d++) {
                float a = fmaf(uq[d], kpT[d][k], vq[d]);
                cp *= a;
                s  += cp;
            }
            float e = exp01(s * 0.2f);
            if (k0 + k > qg1) e = 0.f;          // causal mask
            uint32_t ehat = f2tf32(e);
            Es[q1 * ES_STRIDE + k] = ehat;
            denLocal += __uint_as_float(ehat);
        }
        if (kb < qb) PREFETCH(k0 + 64)
        __syncthreads();

        #pragma unroll
        for (int s = 0; s < 8; s++) {
            const int kk = s * 8;
            uint32_t af[4];
            af[0] = Es[(wm4 + g)     * ES_STRIDE + kk + t];
            af[1] = Es[(wm4 + g + 8) * ES_STRIDE + kk + t];
            af[2] = Es[(wm4 + g)     * ES_STRIDE + kk + t + 4];
            af[3] = Es[(wm4 + g + 8) * ES_STRIDE + kk + t + 4];
            #pragma unroll
            for (int ni = 0; ni < 4; ni++) {
                const int n0 = nb + ni * 8;
                mma_tf32(acc[ni], af,
                         Vt[(kk + t)     * VT_STRIDE + n0 + g],
                         Vt[(kk + t + 4) * VT_STRIDE + n0 + g]);
            }
        }
        __syncthreads();

        if (kb < qb) {
            COMMIT()
            __syncthreads();
        }
    }

    den4[q1][kt] = denLocal;
    __syncthreads();

    const int r0 = wm4 + g;
    const int r1 = r0 + 8;
    float4 d0 = *(const float4*)&den4[r0][0];
    float4 d1 = *(const float4*)&den4[r1][0];
    const float inv0 = 1.f / (d0.x + d0.y + d0.z + d0.w);
    const float inv1 = 1.f / (d1.x + d1.y + d1.z + d1.w);

    float* out0 = g_CTX + (size_t)(b * TT + qb * 64 + r0) * DM + h * DH;
    float* out1 = g_CTX + (size_t)(b * TT + qb * 64 + r1) * DM + h * DH;
    #pragma unroll
    for (int ni = 0; ni < 4; ni++) {
        const int col = nb + ni * 8 + 2 * t;
        *(float2*)(out0 + col) = make_float2(acc[ni].x * inv0, acc[ni].y * inv0);
        *(float2*)(out1 + col) = make_float2(acc[ni].z * inv1, acc[ni].w * inv1);
    }
    #undef PREFETCH
    #undef COMMIT
}

// ---------------------------------------------------------------------------
// Launch
// ---------------------------------------------------------------------------
extern "C" void kernel_launch(void* const* d_in, const int* in_sizes, int n_in,
                              void* d_out, int out_size)
{
    const float* x  = (const float*)d_in[0];
    const float* Wp = (const float*)d_in[1];
    const float* bp = (const float*)d_in[2];
    const float* Wv = (const float*)d_in[3];
    const float* Wo = (const float*)d_in[4];
    float* out = (float*)d_out;

    // V = x@Wv (256 blocks) fused with P = sigmoid(x@Wp+bp) (32 blocks)
    gemm_vp_kernel<<<288, 256>>>(x, Wv, Wp, bp);

    // attention -> CTX (tensor-core PV, tf32 V, prefetch pipeline)
    attn_kernel<<<dim3(TT / 64, BATCH * NH), 256>>>();

    // out = CTX @ Wo (256 blocks)
    gemm_o_kernel<<<dim3(DM / 64, (BATCH * TT) / 128), 256>>>(Wo, out);
}

// round 17
// speedup vs baseline: 1.0635x; 1.0635x over previous
#include <cuda_runtime.h>
#include <cstddef>
#include <cstdint>

// Problem constants
#define BATCH 2
#define TT    1024
#define DM    1024
#define NH    16
#define TD    5
#define DH    64
#define PCOLS (NH * TD)   // 80

// Scratch (no allocation allowed -> __device__ globals)
__device__ float g_P[BATCH * TT * PCOLS];    // sigmoid(x@Wp + bp), (B*T, 80)
__device__ float g_V[BATCH * TT * DM];       // x@Wv,  (B*T, 1024)
__device__ float g_CTX[BATCH * TT * DM];     // attn@V reassembled, (B*T, 1024)

// ---------------------------------------------------------------------------
// tf32 helpers
// ---------------------------------------------------------------------------
__device__ __forceinline__ uint32_t f2tf32(float x) {
    uint32_t r;
    asm("cvt.rna.tf32.f32 %0, %1;" : "=r"(r) : "f"(x));
    return r;
}

__device__ __forceinline__ void mma_tf32(float4& c, const uint32_t a[4],
                                         const uint32_t b0, const uint32_t b1) {
    asm volatile(
        "mma.sync.aligned.m16n8k8.row.col.f32.tf32.tf32.f32 "
        "{%0,%1,%2,%3}, {%4,%5,%6,%7}, {%8,%9}, {%0,%1,%2,%3};"
        : "+f"(c.x), "+f"(c.y), "+f"(c.z), "+f"(c.w)
        : "r"(a[0]), "r"(a[1]), "r"(a[2]), "r"(a[3]), "r"(b0), "r"(b1));
}

// exp(x) for x in (0,1]: e^x = e^0.5 * Taylor6(x-0.5).  |err| ~1.6e-6.
__device__ __forceinline__ float exp01(float x) {
    const float t = x - 0.5f;
    float p = fmaf(t, 1.388888889e-3f, 8.333333333e-3f);
    p = fmaf(p, t, 4.166666667e-2f);
    p = fmaf(p, t, 1.666666667e-1f);
    p = fmaf(p, t, 0.5f);
    p = fmaf(p, t, 1.0f);
    p = fmaf(p, t, 1.0f);
    return 1.6487212707f * p;
}

// ---------------------------------------------------------------------------
// tf32 tensor-core GEMM, packed-fragment smem: C[*,N] = A[*,K] @ B[K,N].
// 128x128 block tile, BK=16, 256 threads = 8 warps (4m x 2n), warp tile 32x64.
//
// Packed layouts (per stage), built at staging time:
//  A4[krow][mcol] : uint4 holding the m16n8k8 A-fragment quad for (krow,mcol):
//    krow = (k>>3)*4 + (k&3)   (k in 0..15, pairs k / k+4)
//    mcol = (m>>4)*8 + (m&7)   (m in 0..127, pairs m / m+8)
//    comp = ((k&4)>>2)*2 + ((m&8)>>3)  -> {a0,a1,a2,a3} order of mma.sync
//  B2[krow][n] : uint2 {B[kb+t][n], B[kb+t+4][n]}, comp = (k&4)>>2
// Fragment fetch: 1 LDS.128 (A, per mi) + 1 LDS.64 (B, per ni):
//   20 LDS/iter/thread vs 48 unpacked. Strides 66 (A) / 132 (B) -> bank-
//   conflict-free (start banks 8t+4g / 8t+2g, distinct per transaction).
// ---------------------------------------------------------------------------
#define BKt   16
#define S4A   66            // uint4 stride of one A4 row
#define S2B   132           // uint2 stride of one B2 row
#define A_ST  (8 * S4A)     // uint4 per A stage (528)
#define B_ST  (8 * S2B)     // uint2 per B stage (1056)

template<int N, int K, bool SIG>
__device__ __forceinline__ void tgemm_body(const float* __restrict__ A,
                                           const float* __restrict__ B,
                                           const float* __restrict__ bias,
                                           float* __restrict__ C,
                                           int bm, int bn,
                                           uint4* sA4, uint2* sB2)
{
    const int tid  = threadIdx.x;          // 0..255
    const int lane = tid & 31;
    const int wid  = tid >> 5;             // 0..7
    const int g    = lane >> 2;
    const int t    = lane & 3;
    const int wm   = (wid >> 1) * 32;      // warp m offset
    const int wn   = (wid & 1) * 64;       // warp n offset
    const int wmc  = (wid >> 1) * 16;      // warp mcol base ((wm>>4)*8)

    // A loader: 2 float4/thread, r = m row, c = k base (mult of 4)
    // per-thread packing constants (k&3 = j inside the float4)
    // B loader: 2 float4/thread, r = k row, cc = n base

    // ---- pack one A float4 (row r, k cols c..c+3) into stage st
    #define PACK_A(st, r_, c_, v_)                                             \
    {                                                                          \
        const int _kr = (((c_) & 8) >> 3) * 4;                                 \
        const int _cp = (((c_) & 4) >> 2) * 2 + (((r_) & 8) >> 3);             \
        const int _mc = ((r_) >> 4) * 8 + ((r_) & 7);                          \
        uint32_t* _b = (uint32_t*)&sA4[(st) * A_ST + _kr * S4A + _mc];         \
        _b[_cp]               = f2tf32((v_).x);                                \
        _b[S4A * 4 + _cp]     = f2tf32((v_).y);                                \
        _b[S4A * 8 + _cp]     = f2tf32((v_).z);                                \
        _b[S4A * 12 + _cp]    = f2tf32((v_).w);                                \
    }

    // ---- pack one B float4 (k row r, n cols cc..cc+3) into stage st
    #define PACK_B(st, r_, cc_, v_)                                            \
    {                                                                          \
        const int _kr = (((r_) & 8) >> 3) * 4 + ((r_) & 3);                    \
        const int _cp = ((r_) & 4) >> 2;                                       \
        uint32_t* _b = (uint32_t*)&sB2[(st) * B_ST + _kr * S2B + (cc_)];       \
        _b[0 * 2 + _cp] = f2tf32((v_).x);                                      \
        _b[1 * 2 + _cp] = f2tf32((v_).y);                                      \
        _b[2 * 2 + _cp] = f2tf32((v_).z);                                      \
        _b[3 * 2 + _cp] = f2tf32((v_).w);                                      \
    }

    // ---- initial tile -> stage 0
    {
        #pragma unroll
        for (int i = 0; i < 2; i++) {
            int f = tid + i * 256, r = f >> 2, c = (f & 3) * 4;
            float4 v = *(const float4*)(A + (size_t)(bm + r) * K + c);
            PACK_A(0, r, c, v)
        }
        #pragma unroll
        for (int i = 0; i < 2; i++) {
            int f = tid + i * 256, r = f >> 5, c = (f & 31) * 4;
            float4 v = (bn + c < N)
                     ? *(const float4*)(B + (size_t)r * N + bn + c)
                     : make_float4(0.f, 0.f, 0.f, 0.f);
            PACK_B(0, r, c, v)
        }
    }
    __syncthreads();

    float4 acc[2][8];
    #pragma unroll
    for (int mi = 0; mi < 2; mi++)
        #pragma unroll
        for (int ni = 0; ni < 8; ni++)
            acc[mi][ni] = make_float4(0.f, 0.f, 0.f, 0.f);

    float4 pa[2], pb[2];
    int cur = 0;
    for (int k0 = 0; k0 < K; k0 += BKt) {
        const bool more = (k0 + BKt) < K;
        if (more) {   // prefetch next tile into registers (raw fp32)
            #pragma unroll
            for (int i = 0; i < 2; i++) {
                int f = tid + i * 256, r = f >> 2, c = (f & 3) * 4;
                pa[i] = *(const float4*)(A + (size_t)(bm + r) * K + k0 + BKt + c);
            }
            #pragma unroll
            for (int i = 0; i < 2; i++) {
                int f = tid + i * 256, r = f >> 5, c = (f & 31) * 4;
                pb[i] = (bn + c < N)
                      ? *(const float4*)(B + (size_t)(k0 + BKt + r) * N + bn + c)
                      : make_float4(0.f, 0.f, 0.f, 0.f);
            }
        }
        // ---- compute on current stage: 2 k8 sub-steps, packed fragments
        #pragma unroll
        for (int s = 0; s < 2; s++) {
            const int kr = s * 4 + t;
            uint4 af0 = sA4[cur * A_ST + kr * S4A + wmc + g];
            uint4 af1 = sA4[cur * A_ST + kr * S4A + wmc + 8 + g];
            uint2 bf[8];
            #pragma unroll
            for (int ni = 0; ni < 8; ni++)
                bf[ni] = sB2[cur * B_ST + kr * S2B + wn + ni * 8 + g];
            #pragma unroll
            for (int ni = 0; ni < 8; ni++) {
                mma_tf32(acc[0][ni], (const uint32_t*)&af0, bf[ni].x, bf[ni].y);
                mma_tf32(acc[1][ni], (const uint32_t*)&af1, bf[ni].x, bf[ni].y);
            }
        }
        if (more) {   // commit prefetched tile to the other stage
            int nxt = cur ^ 1;
            #pragma unroll
            for (int i = 0; i < 2; i++) {
                int f = tid + i * 256, r = f >> 2, c = (f & 3) * 4;
                PACK_A(nxt, r, c, pa[i])
            }
            #pragma unroll
            for (int i = 0; i < 2; i++) {
                int f = tid + i * 256, r = f >> 5, c = (f & 31) * 4;
                PACK_B(nxt, r, c, pb[i])
            }
            __syncthreads();
            cur = nxt;
        }
    }

    // ---- epilogue from fragments (float2 stores)
    #pragma unroll
    for (int mi = 0; mi < 2; mi++) {
        const int r0 = bm + wm + mi * 16 + g;
        #pragma unroll
        for (int ni = 0; ni < 8; ni++) {
            const int col = bn + wn + ni * 8 + 2 * t;
            if (col < N) {
                float2 lo = make_float2(acc[mi][ni].x, acc[mi][ni].y);
                float2 hi = make_float2(acc[mi][ni].z, acc[mi][ni].w);
                if (SIG) {
                    lo.x = 1.f / (1.f + __expf(-(lo.x + bias[col + 0])));
                    lo.y = 1.f / (1.f + __expf(-(lo.y + bias[col + 1])));
                    hi.x = 1.f / (1.f + __expf(-(hi.x + bias[col + 0])));
                    hi.y = 1.f / (1.f + __expf(-(hi.y + bias[col + 1])));
                }
                *(float2*)(C + (size_t)r0 * N + col)       = lo;
                *(float2*)(C + (size_t)(r0 + 8) * N + col) = hi;
            }
        }
    }
    #undef PACK_A
    #undef PACK_B
}

// Fused V + P GEMM: blocks 0..127 do V = x@Wv, blocks 128..143 do
// P = sigmoid(x@Wp + bp). One wave on 148 SMs (R14 validated grid).
__global__ __launch_bounds__(256)
void gemm_vp_kernel(const float* __restrict__ x, const float* __restrict__ Wv,
                    const float* __restrict__ Wp, const float* __restrict__ bp)
{
    __shared__ uint4 sA4[2 * A_ST];
    __shared__ uint2 sB2[2 * B_ST];
    const int bid = blockIdx.x;
    if (bid < 128)
        tgemm_body<DM, DM, false>(x, Wv, nullptr, g_V,
                                  (bid >> 3) * 128, (bid & 7) * 128, sA4, sB2);
    else
        tgemm_body<PCOLS, DM, true>(x, Wp, bp, g_P,
                                    (bid - 128) * 128, 0, sA4, sB2);
}

__global__ __launch_bounds__(256)
void gemm_o_kernel(const float* __restrict__ Wo, float* __restrict__ out)
{
    __shared__ uint4 sA4[2 * A_ST];
    __shared__ uint2 sB2[2 * B_ST];
    tgemm_body<DM, DM, false>(g_CTX, Wo, nullptr, out,
                              blockIdx.y * 128, blockIdx.x * 128, sA4, sB2);
}

// ---------------------------------------------------------------------------
// Attention with tensor-core PV (validated R14 config, unchanged).
// ---------------------------------------------------------------------------
#define ES_STRIDE 68
#define VT_STRIDE 72

__global__ __launch_bounds__(256)
void attn_kernel()
{
    __shared__ uint32_t Es[64 * ES_STRIDE];   // exp-sim, tf32, row-major [q][k]
    __shared__ uint32_t Vt[64 * VT_STRIDE];   // V tile, tf32 [k][d]
    __shared__ float    kpT[TD][64];          // transposed key paths
    __shared__ float    den4[64][4];          // per-row denom partials

    const int bh = blockIdx.y;
    const int b  = bh >> 4;
    const int h  = bh & 15;
    const int qb = gridDim.x - 1 - blockIdx.x;   // heavy blocks first
    const int tid = threadIdx.x;
    const int lane = tid & 31;
    const int wid  = tid >> 5;
    const int g    = lane >> 2;
    const int t    = lane & 3;

    const int q1 = tid >> 2;
    const int kt = tid & 3;
    const int qg1 = qb * 64 + q1;
    const int wm4 = (wid >> 1) * 16;
    const int nb  = (wid & 1) * 32;

    const int vr0 = tid >> 4;
    const int vc4 = tid & 15;
    const int kd  = tid >> 6;
    const int kkk = tid & 63;

    float uq[TD], vq[TD];
    {
        const float* prow = g_P + (size_t)(b * TT + qg1) * PCOLS + h * TD;
        #pragma unroll
        for (int d = 0; d < TD; d++) {
            float p = prow[d];
            uq[d] = 2.f * p - 1.f;
            vq[d] = 1.f - p;
        }
    }

    float4 acc[4];
    #pragma unroll
    for (int i = 0; i < 4; i++) acc[i] = make_float4(0.f, 0.f, 0.f, 0.f);
    float denLocal = 0.f;

    float4 pv[4];
    float  pk0 = 0.f, pk1 = 0.f;

    #define PREFETCH(k0_)                                                      \
    {                                                                          \
        _Pragma("unroll")                                                      \
        for (int i = 0; i < 4; i++) {                                          \
            pv[i] = *(const float4*)(g_V + (size_t)(b * TT + (k0_) + vr0 +     \
                                     i * 16) * DM + h * DH + vc4 * 4);         \
        }                                                                      \
        pk0 = g_P[(size_t)(b * TT + (k0_) + kkk) * PCOLS + h * TD + kd];       \
        if (tid < 64)                                                          \
            pk1 = g_P[(size_t)(b * TT + (k0_) + tid) * PCOLS + h * TD + 4];    \
    }

    #define COMMIT()                                                           \
    {                                                                          \
        _Pragma("unroll")                                                      \
        for (int i = 0; i < 4; i++) {                                          \
            uint32_t* dst = &Vt[(vr0 + i * 16) * VT_STRIDE + vc4 * 4];         \
            dst[0] = f2tf32(pv[i].x); dst[1] = f2tf32(pv[i].y);                \
            dst[2] = f2tf32(pv[i].z); dst[3] = f2tf32(pv[i].w);                \
        }                                                                      \
        kpT[kd][kkk] = pk0;                                                    \
        if (tid < 64) kpT[4][tid] = pk1;                                       \
    }

    PREFETCH(0)
    COMMIT()
    __syncthreads();

    for (int kb = 0; kb <= qb; kb++) {
        const int k0 = kb * 64;

        #pragma unroll
        for (int j = 0; j < 16; j++) {
            const int k = kt * 16 + j;
            float cp = 1.f, s = 0.f;
            #pragma unroll
            for (int d = 0; d < TD; d++) {
                float a = fmaf(uq[d], kpT[d][k], vq[d]);
                cp *= a;
                s  += cp;
            }
            float e = exp01(s * 0.2f);
            if (k0 + k > qg1) e = 0.f;          // causal mask
            uint32_t ehat = f2tf32(e);
            Es[q1 * ES_STRIDE + k] = ehat;
            denLocal += __uint_as_float(ehat);
        }
        if (kb < qb) PREFETCH(k0 + 64)
        __syncthreads();

        #pragma unroll
        for (int s = 0; s < 8; s++) {
            const int kk = s * 8;
            uint32_t af[4];
            af[0] = Es[(wm4 + g)     * ES_STRIDE + kk + t];
            af[1] = Es[(wm4 + g + 8) * ES_STRIDE + kk + t];
            af[2] = Es[(wm4 + g)     * ES_STRIDE + kk + t + 4];
            af[3] = Es[(wm4 + g + 8) * ES_STRIDE + kk + t + 4];
            #pragma unroll
            for (int ni = 0; ni < 4; ni++) {
                const int n0 = nb + ni * 8;
                mma_tf32(acc[ni], af,
                         Vt[(kk + t)     * VT_STRIDE + n0 + g],
                         Vt[(kk + t + 4) * VT_STRIDE + n0 + g]);
            }
        }
        __syncthreads();

        if (kb < qb) {
            COMMIT()
            __syncthreads();
        }
    }

    den4[q1][kt] = denLocal;
    __syncthreads();

    const int r0 = wm4 + g;
    const int r1 = r0 + 8;
    float4 d0 = *(const float4*)&den4[r0][0];
    float4 d1 = *(const float4*)&den4[r1][0];
    const float inv0 = 1.f / (d0.x + d0.y + d0.z + d0.w);
    const float inv1 = 1.f / (d1.x + d1.y + d1.z + d1.w);

    float* out0 = g_CTX + (size_t)(b * TT + qb * 64 + r0) * DM + h * DH;
    float* out1 = g_CTX + (size_t)(b * TT + qb * 64 + r1) * DM + h * DH;
    #pragma unroll
    for (int ni = 0; ni < 4; ni++) {
        const int col = nb + ni * 8 + 2 * t;
        *(float2*)(out0 + col) = make_float2(acc[ni].x * inv0, acc[ni].y * inv0);
        *(float2*)(out1 + col) = make_float2(acc[ni].z * inv1, acc[ni].w * inv1);
    }
    #undef PREFETCH
    #undef COMMIT
}

// ---------------------------------------------------------------------------
// Launch
// ---------------------------------------------------------------------------
extern "C" void kernel_launch(void* const* d_in, const int* in_sizes, int n_in,
                              void* d_out, int out_size)
{
    const float* x  = (const float*)d_in[0];
    const float* Wp = (const float*)d_in[1];
    const float* bp = (const float*)d_in[2];
    const float* Wv = (const float*)d_in[3];
    const float* Wo = (const float*)d_in[4];
    float* out = (float*)d_out;

    // V = x@Wv (128 blocks) fused with P = sigmoid(x@Wp+bp) (16 blocks)
    gemm_vp_kernel<<<144, 256>>>(x, Wv, Wp, bp);

    // attention -> CTX (tensor-core PV, tf32 V, prefetch pipeline)
    attn_kernel<<<dim3(TT / 64, BATCH * NH), 256>>>();

    // out = CTX @ Wo
    gemm_o_kernel<<<dim3(DM / 128, (BATCH * TT) / 128), 256>>>(Wo, out);
}